// round 14
// baseline (speedup 1.0000x reference)
#include <cuda_runtime.h>
#include <cuda_bf16.h>
#include <cstdint>

#define NN 50000
#define NE 800000
#define DD 128
#define NTILES 391    // ceil(NN/128)
#define GRID_GEMM 148
#define ELLW 64       // padded row width (P(deg>64) ~ 1e-21 for Poisson(16))

// Scratch (static __device__ arrays: allocation-free)
static __device__ float g_x1 [(size_t)NN * DD];
static __device__ float g_x2 [(size_t)NN * DD];
static __device__ int   g_cursor[NN];             // bump cursor == degree after fill
static __device__ int   g_ell[(size_t)NN * ELLW]; // padded adjacency
// bf16 hi/lo planes, pre-swizzled 16KB tile-planes (128 rows x 128B)
static __device__ uint4 g_aggh4[2 * NTILES * 1024];   // agg chunks 0-1
static __device__ uint4 g_aggl4[2 * NTILES * 1024];
static __device__ uint4 g_wh4[12 * 1024];             // 3 layers x 4 chunks
static __device__ uint4 g_wl4[12 * 1024];

// split one float4 into bf16 hi/lo, swizzled 8B stores at (row, q)
__device__ __forceinline__ void st_hl(char* hiBase, char* loBase, int row, int q, float4 v) {
    __nv_bfloat16 hx = __float2bfloat16_rn(v.x);
    __nv_bfloat16 hy = __float2bfloat16_rn(v.y);
    __nv_bfloat16 hz = __float2bfloat16_rn(v.z);
    __nv_bfloat16 hw = __float2bfloat16_rn(v.w);
    __nv_bfloat16 lx = __float2bfloat16_rn(v.x - __bfloat162float(hx));
    __nv_bfloat16 ly = __float2bfloat16_rn(v.y - __bfloat162float(hy));
    __nv_bfloat16 lz = __float2bfloat16_rn(v.z - __bfloat162float(hz));
    __nv_bfloat16 lw = __float2bfloat16_rn(v.w - __bfloat162float(hw));
    __nv_bfloat162 H01, H23, L01, L23;
    H01.x = hx; H01.y = hy; H23.x = hz; H23.y = hw;
    L01.x = lx; L01.y = ly; L23.x = lz; L23.y = lw;
    int off = row * 128 + q * 8;
    int sw = off ^ ((off >> 3) & 0x70);
    uint2 Hw, Lw;
    Hw.x = *(uint32_t*)&H01; Hw.y = *(uint32_t*)&H23;
    Lw.x = *(uint32_t*)&L01; Lw.y = *(uint32_t*)&L23;
    *(uint2*)(hiBase + sw) = Hw;
    *(uint2*)(loBase + sw) = Lw;
}

// ---------------- W pre-split (96 blocks) ----------------
__global__ void k_setup(const float* __restrict__ Wl0, const float* __restrict__ Wr0,
                        const float* __restrict__ Wl1, const float* __restrict__ Wr1,
                        const float* __restrict__ Wl2, const float* __restrict__ Wr2) {
    int idx = blockIdx.x * 256 + threadIdx.x;   // 0..24575 (3 layers x 8192)
    int layer = idx >> 13;
    int rem13 = idx & 8191;
    int w     = rem13 >> 12;           // 0: Wl, 1: Wr
    int rem   = rem13 & 4095;
    int row   = rem >> 5;              // out-dim 0..127
    int slot  = rem & 31;              // float4 slot across 128 in-dims
    int chunk = w * 2 + (slot >> 4);
    int q     = slot & 15;
    const float* W = (layer == 0) ? (w ? Wr0 : Wl0)
                   : (layer == 1) ? (w ? Wr1 : Wl1)
                                  : (w ? Wr2 : Wl2);
    float4 v = __ldg((const float4*)(W + (size_t)row * DD) + slot);
    char* hb = (char*)g_wh4 + (size_t)(layer * 4 + chunk) * 16384;
    char* lb = (char*)g_wl4 + (size_t)(layer * 4 + chunk) * 16384;
    st_hl(hb, lb, row, q, v);
}

// ---------------- fill padded adjacency: 4 edges per thread ----------------
__global__ void k_fill(const int* __restrict__ row, const int* __restrict__ col) {
    int e4 = blockIdx.x * blockDim.x + threadIdx.x;
    if (e4 < NE / 4) {
        int4 r = __ldg((const int4*)row + e4);
        int4 c = __ldg((const int4*)col + e4);
        int p0 = atomicAdd(&g_cursor[r.x], 1);
        int p1 = atomicAdd(&g_cursor[r.y], 1);
        int p2 = atomicAdd(&g_cursor[r.z], 1);
        int p3 = atomicAdd(&g_cursor[r.w], 1);
        g_ell[(size_t)r.x * ELLW + p0] = c.x;
        g_ell[(size_t)r.y * ELLW + p1] = c.y;
        g_ell[(size_t)r.z * ELLW + p2] = c.z;
        g_ell[(size_t)r.w * ELLW + p3] = c.w;
    }
}

// ---------------- gather: agg planes = split(invdeg[n] * sum_nbr maybe_relu(src[c])) ----------------
#define RELU4(v)                                                  \
    do {                                                          \
        (v).x = fmaxf((v).x, 0.f); (v).y = fmaxf((v).y, 0.f);     \
        (v).z = fmaxf((v).z, 0.f); (v).w = fmaxf((v).w, 0.f);     \
    } while (0)
#define ACC4(a, v)                                                \
    do {                                                          \
        (a).x += (v).x; (a).y += (v).y;                           \
        (a).z += (v).z; (a).w += (v).w;                           \
    } while (0)

template <bool RELU>
__global__ void __launch_bounds__(256) k_gather(const float* __restrict__ src) {
    int w    = (blockIdx.x * blockDim.x + threadIdx.x) >> 5;
    int lane = threadIdx.x & 31;
    if (w >= NN) return;
    const int n = __ldg(g_cursor + w);          // degree
    const int* cols = g_ell + (size_t)w * ELLW;

    float4 a0 = make_float4(0.f, 0.f, 0.f, 0.f);
    float4 a1 = a0, a2 = a0, a3 = a0;
    int i = 0;
    for (; i + 7 < n; i += 8) {
        int c0 = __ldg(cols + i);
        int c1 = __ldg(cols + i + 1);
        int c2 = __ldg(cols + i + 2);
        int c3 = __ldg(cols + i + 3);
        int c4 = __ldg(cols + i + 4);
        int c5 = __ldg(cols + i + 5);
        int c6 = __ldg(cols + i + 6);
        int c7 = __ldg(cols + i + 7);
        float4 v0 = __ldg((const float4*)(src + (size_t)c0 * DD) + lane);
        float4 v1 = __ldg((const float4*)(src + (size_t)c1 * DD) + lane);
        float4 v2 = __ldg((const float4*)(src + (size_t)c2 * DD) + lane);
        float4 v3 = __ldg((const float4*)(src + (size_t)c3 * DD) + lane);
        float4 v4 = __ldg((const float4*)(src + (size_t)c4 * DD) + lane);
        float4 v5 = __ldg((const float4*)(src + (size_t)c5 * DD) + lane);
        float4 v6 = __ldg((const float4*)(src + (size_t)c6 * DD) + lane);
        float4 v7 = __ldg((const float4*)(src + (size_t)c7 * DD) + lane);
        if (RELU) {
            RELU4(v0); RELU4(v1); RELU4(v2); RELU4(v3);
            RELU4(v4); RELU4(v5); RELU4(v6); RELU4(v7);
        }
        ACC4(a0, v0); ACC4(a1, v1); ACC4(a2, v2); ACC4(a3, v3);
        ACC4(a0, v4); ACC4(a1, v5); ACC4(a2, v6); ACC4(a3, v7);
    }
    for (; i + 3 < n; i += 4) {
        int c0 = __ldg(cols + i);
        int c1 = __ldg(cols + i + 1);
        int c2 = __ldg(cols + i + 2);
        int c3 = __ldg(cols + i + 3);
        float4 v0 = __ldg((const float4*)(src + (size_t)c0 * DD) + lane);
        float4 v1 = __ldg((const float4*)(src + (size_t)c1 * DD) + lane);
        float4 v2 = __ldg((const float4*)(src + (size_t)c2 * DD) + lane);
        float4 v3 = __ldg((const float4*)(src + (size_t)c3 * DD) + lane);
        if (RELU) { RELU4(v0); RELU4(v1); RELU4(v2); RELU4(v3); }
        ACC4(a0, v0); ACC4(a1, v1); ACC4(a2, v2); ACC4(a3, v3);
    }
    for (; i < n; i++) {
        int c0 = __ldg(cols + i);
        float4 v0 = __ldg((const float4*)(src + (size_t)c0 * DD) + lane);
        if (RELU) RELU4(v0);
        ACC4(a0, v0);
    }

    float s = 1.0f / fmaxf((float)n, 1.0f);
    float4 acc;
    acc.x = ((a0.x + a1.x) + (a2.x + a3.x)) * s;
    acc.y = ((a0.y + a1.y) + (a2.y + a3.y)) * s;
    acc.z = ((a0.z + a1.z) + (a2.z + a3.z)) * s;
    acc.w = ((a0.w + a1.w) + (a2.w + a3.w)) * s;

    // split + swizzled store into agg tile-planes
    int tile  = w >> 7;
    int rowt  = w & 127;
    int chunk = lane >> 4;      // k-half
    int q     = lane & 15;
    char* hb = (char*)g_aggh4 + (size_t)(chunk * NTILES + tile) * 16384;
    char* lb = (char*)g_aggl4 + (size_t)(chunk * NTILES + tile) * 16384;
    st_hl(hb, lb, rowt, q, acc);
}

// ================= persistent mma.sync bf16-split GEMM (pipelined fill) =================
// Grid 148, 1 CTA/SM, 256 threads. W planes (128KB) resident in smem;
// A-chunk fills are register-prefetched: LDG for chunk c+1 issued before mma of
// chunk c, hiding L2 latency behind tensor work. Single A buffer (32KB).

#define OFF_BIAS 0
#define OFF_B    1024                       // 8 planes x 16KB
#define OFF_AHI  (1024 + 131072)
#define OFF_ALO  (1024 + 131072 + 16384)
#define SMEM_GEMM (1024 + 131072 + 32768)   // 164864

__device__ __forceinline__ uint32_t s2u(const void* p) {
    uint32_t a;
    asm("{ .reg .u64 t; cvta.to.shared.u64 t, %1; cvt.u32.u64 %0, t; }" : "=r"(a) : "l"(p));
    return a;
}
__device__ __forceinline__ void ldsm4(uint32_t& r0, uint32_t& r1, uint32_t& r2, uint32_t& r3,
                                      uint32_t addr) {
    asm volatile("ldmatrix.sync.aligned.m8n8.x4.shared.b16 {%0,%1,%2,%3}, [%4];"
                 : "=r"(r0), "=r"(r1), "=r"(r2), "=r"(r3) : "r"(addr));
}
__device__ __forceinline__ void mma16816(float* d, const uint32_t* a, const uint32_t* b) {
    asm volatile("mma.sync.aligned.m16n8k16.row.col.f32.bf16.bf16.f32 "
                 "{%0,%1,%2,%3}, {%4,%5,%6,%7}, {%8,%9}, {%0,%1,%2,%3};"
                 : "+f"(d[0]), "+f"(d[1]), "+f"(d[2]), "+f"(d[3])
                 : "r"(a[0]), "r"(a[1]), "r"(a[2]), "r"(a[3]), "r"(b[0]), "r"(b[1]));
}
__device__ __forceinline__ uint32_t tile_addr(uint32_t planeBase, int lane, int r0, int k0) {
    int rr = r0 + (lane & 15);
    int kk = k0 + ((lane >> 4) << 3);
    uint32_t off = rr * 128 + kk * 2;
    return planeBase + (off ^ ((off >> 3) & 0x70));
}

// prefetch agg chunk (c<2) of a tile into 8 uint4 regs
__device__ __forceinline__ void pf_agg(uint4* pf, int c, int tile, int t) {
    const uint4* ah = g_aggh4 + (size_t)(c * NTILES + tile) * 1024;
    const uint4* al = g_aggl4 + (size_t)(c * NTILES + tile) * 1024;
#pragma unroll
    for (int u = 0; u < 4; u++) {
        pf[u]     = __ldg(ah + t + u * 256);
        pf[4 + u] = __ldg(al + t + u * 256);
    }
}
// prefetch fp32 h half (0/1) of a tile into 8 float4 regs (as uint4)
__device__ __forceinline__ void pf_h(uint4* pf, const float* h, int half, int rowBase, int t) {
#pragma unroll
    for (int u = 0; u < 8; u++) {
        int idx = t + u * 256;
        int row = idx >> 4, q = idx & 15;
        int gi = rowBase + row;
        float4 va = make_float4(0.f, 0.f, 0.f, 0.f);
        if (gi < NN)
            va = __ldg((const float4*)(h + (size_t)gi * DD + half * 64) + q);
        pf[u] = *(uint4*)&va;
    }
}

template <bool RELU, bool RES>
__global__ void __launch_bounds__(256)
k_gemm_mma(const float* __restrict__ h, int layer, const float* __restrict__ bias,
           float* __restrict__ out)
{
    extern __shared__ char smem[];
    const uint32_t sb = s2u(smem);
    const int t    = threadIdx.x;
    const int wid  = t >> 5;
    const int lane = t & 31;
    const int wm = (wid >> 2) * 64;
    const int wn = (wid & 3) * 32;

    if (t < 128) ((float*)(smem + OFF_BIAS))[t] = bias[t];

    // ---- load ALL W planes once: 8192 uint4 ----
    {
        uint4* sB = (uint4*)(smem + OFF_B);
#pragma unroll
        for (int u = 0; u < 32; u++) {
            int idx = t + u * 256;          // 0..8191
            int p   = idx >> 10;            // plane 0..7
            int r   = idx & 1023;
            int c   = p >> 1;
            const uint4* src = (p & 1) ? (g_wl4 + (size_t)(layer * 4 + c) * 1024)
                                       : (g_wh4 + (size_t)(layer * 4 + c) * 1024);
            sB[idx] = __ldg(src + r);
        }
    }

    uint4* sAh = (uint4*)(smem + OFF_AHI);
    uint4* sAl = (uint4*)(smem + OFF_ALO);
    const float* bsh = (const float*)(smem + OFF_BIAS);
    const int tr = lane >> 2;
    const int tc = (lane & 3) * 2;

    uint4 pf[8];
    if (blockIdx.x < NTILES) pf_agg(pf, 0, blockIdx.x, t);

    for (int tile = blockIdx.x; tile < NTILES; tile += GRID_GEMM) {
        const int rowBase = tile * 128;
        float acc[4][4][4];
#pragma unroll
        for (int i = 0; i < 4; i++)
#pragma unroll
            for (int j = 0; j < 4; j++)
#pragma unroll
                for (int q = 0; q < 4; q++) acc[i][j][q] = 0.f;

        for (int c = 0; c < 4; c++) {
            __syncthreads();   // previous chunk's mma (or prev tile epilogue) done
            // ---- store prefetched chunk c into A planes ----
            if (c < 2) {
#pragma unroll
                for (int u = 0; u < 4; u++) {
                    sAh[t + u * 256] = pf[u];
                    sAl[t + u * 256] = pf[4 + u];
                }
            } else {
#pragma unroll
                for (int u = 0; u < 8; u++) {
                    int idx = t + u * 256;
                    int row = idx >> 4, q = idx & 15;
                    float4 va = *(float4*)&pf[u];
                    if (RELU) RELU4(va);
                    st_hl(smem + OFF_AHI, smem + OFF_ALO, row, q, va);
                }
            }
            __syncthreads();
            // ---- issue prefetch for next chunk (overlaps with mma below) ----
            if (c == 0) {
                pf_agg(pf, 1, tile, t);
            } else if (c < 3) {
                pf_h(pf, h, c - 1, rowBase, t);   // c=1 -> half0 (chunk2), c=2 -> half1 (chunk3)
            } else {
                int ntile = tile + GRID_GEMM;
                if (ntile < NTILES) pf_agg(pf, 0, ntile, t);
            }

            const uint32_t bHiBase = sb + OFF_B + c * 32768;
            const uint32_t bLoBase = bHiBase + 16384;
#pragma unroll
            for (int ks = 0; ks < 4; ks++) {
                const int k0 = ks * 16;
                uint32_t bhi[4][2], blo[4][2];
#pragma unroll
                for (int p = 0; p < 2; p++) {
                    uint32_t r0, r1, r2, r3;
                    ldsm4(r0, r1, r2, r3, tile_addr(bHiBase, lane, wn + p * 16, k0));
                    bhi[2 * p][0] = r0;     bhi[2 * p][1] = r2;
                    bhi[2 * p + 1][0] = r1; bhi[2 * p + 1][1] = r3;
                    ldsm4(r0, r1, r2, r3, tile_addr(bLoBase, lane, wn + p * 16, k0));
                    blo[2 * p][0] = r0;     blo[2 * p][1] = r2;
                    blo[2 * p + 1][0] = r1; blo[2 * p + 1][1] = r3;
                }
#pragma unroll
                for (int i = 0; i < 4; i++) {
                    uint32_t ahi[4], alo[4];
                    ldsm4(ahi[0], ahi[1], ahi[2], ahi[3],
                          tile_addr(sb + OFF_AHI, lane, wm + i * 16, k0));
                    ldsm4(alo[0], alo[1], alo[2], alo[3],
                          tile_addr(sb + OFF_ALO, lane, wm + i * 16, k0));
#pragma unroll
                    for (int j = 0; j < 4; j++) {
                        mma16816(acc[i][j], ahi, bhi[j]);
                        mma16816(acc[i][j], ahi, blo[j]);
                        mma16816(acc[i][j], alo, bhi[j]);
                    }
                }
            }
        }

        // ---- epilogue: bias (+ residual), direct register->gmem ----
#pragma unroll
        for (int i = 0; i < 4; i++) {
#pragma unroll
            for (int half = 0; half < 2; half++) {
                int gi = rowBase + wm + i * 16 + tr + half * 8;
                if (gi >= NN) continue;
#pragma unroll
                for (int j = 0; j < 4; j++) {
                    int col = wn + j * 8 + tc;
                    float2 o;
                    o.x = acc[i][j][half * 2]     + bsh[col];
                    o.y = acc[i][j][half * 2 + 1] + bsh[col + 1];
                    if (RES) {
                        float2 rv = __ldg((const float2*)(h + (size_t)gi * DD + col));
                        o.x += rv.x; o.y += rv.y;
                    }
                    *(float2*)(out + (size_t)gi * DD + col) = o;
                }
            }
        }
    }
}

// ---------------- launch ----------------
extern "C" void kernel_launch(void* const* d_in, const int* in_sizes, int n_in,
                              void* d_out, int out_size) {
    const float* x    = (const float*)d_in[0];
    const int*   erow = (const int*)  d_in[1];
    const int*   ecol = (const int*)  d_in[2];
    const float* Wl0 = (const float*)d_in[3];
    const float* Wr0 = (const float*)d_in[4];
    const float* b0  = (const float*)d_in[5];
    const float* Wl1 = (const float*)d_in[6];
    const float* Wr1 = (const float*)d_in[7];
    const float* b1  = (const float*)d_in[8];
    const float* Wl2 = (const float*)d_in[9];
    const float* Wr2 = (const float*)d_in[10];
    const float* b2  = (const float*)d_in[11];
    float* out = (float*)d_out;

    float *p_x1 = nullptr, *p_x2 = nullptr;
    void* p_cursor = nullptr;
    cudaGetSymbolAddress((void**)&p_x1, g_x1);
    cudaGetSymbolAddress((void**)&p_x2, g_x2);
    cudaGetSymbolAddress(&p_cursor, g_cursor);

    cudaFuncSetAttribute(k_gemm_mma<false, false>,
                         cudaFuncAttributeMaxDynamicSharedMemorySize, SMEM_GEMM);
    cudaFuncSetAttribute(k_gemm_mma<true, true>,
                         cudaFuncAttributeMaxDynamicSharedMemorySize, SMEM_GEMM);

    const int edge4Blocks  = (NE / 4 + 255) / 256;      // 782
    const int gatherBlocks = (NN * 32 + 255) / 256;     // 6250

    // adjacency build: zero cursors (memset node), W pre-split, bump-fill
    cudaMemsetAsync(p_cursor, 0, NN * sizeof(int));
    k_setup<<<96, 256>>>(Wl0, Wr0, Wl1, Wr1, Wl2, Wr2);
    k_fill<<<edge4Blocks, 256>>>(erow, ecol);

    // ---- layer 0: x1 = sage(x) ----
    k_gather<false><<<gatherBlocks, 256>>>(x);
    k_gemm_mma<false, false><<<GRID_GEMM, 256, SMEM_GEMM>>>(x, 0, b0, p_x1);

    // ---- layer 1: x2 = sage(relu(x1)) + x1 ----
    k_gather<true><<<gatherBlocks, 256>>>(p_x1);
    k_gemm_mma<true, true><<<GRID_GEMM, 256, SMEM_GEMM>>>(p_x1, 1, b1, p_x2);

    // ---- layer 2: out = sage(relu(x2)) + x2 ----
    k_gather<true><<<gatherBlocks, 256>>>(p_x2);
    k_gemm_mma<true, true><<<GRID_GEMM, 256, SMEM_GEMM>>>(p_x2, 2, b2, out);
}

// round 15
// speedup vs baseline: 1.0620x; 1.0620x over previous
#include <cuda_runtime.h>
#include <cuda_bf16.h>
#include <cstdint>

#define NN 50000
#define NE 800000
#define DD 128
#define NTILES 391    // ceil(NN/128)
#define NB 196        // ceil(NN/256)
#define GRID_GEMM 148

// Scratch (static __device__ arrays: allocation-free)
static __device__ float g_x1 [(size_t)NN * DD];
static __device__ float g_x2 [(size_t)NN * DD];
static __device__ float g_invdeg[NN];
static __device__ int   g_deg[NN];
static __device__ int   g_rowptr[NN + 1];
static __device__ int   g_cursor[NN];
static __device__ int   g_csr_col[NE];
static __device__ int   g_bsum[NB];
// bf16 hi/lo planes, pre-swizzled 16KB tile-planes (128 rows x 128B)
static __device__ uint4 g_aggh4[2 * NTILES * 1024];   // agg chunks 0-1
static __device__ uint4 g_aggl4[2 * NTILES * 1024];
static __device__ uint4 g_wh4[12 * 1024];             // 3 layers x 4 chunks
static __device__ uint4 g_wl4[12 * 1024];

// split one float4 into bf16 hi/lo, swizzled 8B stores at (row, q)
__device__ __forceinline__ void st_hl(char* hiBase, char* loBase, int row, int q, float4 v) {
    __nv_bfloat16 hx = __float2bfloat16_rn(v.x);
    __nv_bfloat16 hy = __float2bfloat16_rn(v.y);
    __nv_bfloat16 hz = __float2bfloat16_rn(v.z);
    __nv_bfloat16 hw = __float2bfloat16_rn(v.w);
    __nv_bfloat16 lx = __float2bfloat16_rn(v.x - __bfloat162float(hx));
    __nv_bfloat16 ly = __float2bfloat16_rn(v.y - __bfloat162float(hy));
    __nv_bfloat16 lz = __float2bfloat16_rn(v.z - __bfloat162float(hz));
    __nv_bfloat16 lw = __float2bfloat16_rn(v.w - __bfloat162float(hw));
    __nv_bfloat162 H01, H23, L01, L23;
    H01.x = hx; H01.y = hy; H23.x = hz; H23.y = hw;
    L01.x = lx; L01.y = ly; L23.x = lz; L23.y = lw;
    int off = row * 128 + q * 8;
    int sw = off ^ ((off >> 3) & 0x70);
    uint2 Hw, Lw;
    Hw.x = *(uint32_t*)&H01; Hw.y = *(uint32_t*)&H23;
    Lw.x = *(uint32_t*)&L01; Lw.y = *(uint32_t*)&L23;
    *(uint2*)(hiBase + sw) = Hw;
    *(uint2*)(loBase + sw) = Lw;
}

// ---------------- fused setup: zero deg (blocks 0..195) + pre-split W (blocks 196..291) ----------------
__global__ void k_setup(const float* __restrict__ Wl0, const float* __restrict__ Wr0,
                        const float* __restrict__ Wl1, const float* __restrict__ Wr1,
                        const float* __restrict__ Wl2, const float* __restrict__ Wr2) {
    int b = blockIdx.x;
    int t = threadIdx.x;
    if (b < NB) {
        int i = b * 256 + t;
        if (i < NN) g_deg[i] = 0;
    } else {
        int idx = (b - NB) * 256 + t;      // 0..24575 (3 layers x 8192)
        int layer = idx >> 13;
        int rem13 = idx & 8191;
        int w     = rem13 >> 12;           // 0: Wl, 1: Wr
        int rem   = rem13 & 4095;
        int row   = rem >> 5;              // out-dim 0..127
        int slot  = rem & 31;              // float4 slot across 128 in-dims
        int chunk = w * 2 + (slot >> 4);
        int q     = slot & 15;
        const float* W = (layer == 0) ? (w ? Wr0 : Wl0)
                       : (layer == 1) ? (w ? Wr1 : Wl1)
                                      : (w ? Wr2 : Wl2);
        float4 v = __ldg((const float4*)(W + (size_t)row * DD) + slot);
        char* hb = (char*)g_wh4 + (size_t)(layer * 4 + chunk) * 16384;
        char* lb = (char*)g_wl4 + (size_t)(layer * 4 + chunk) * 16384;
        st_hl(hb, lb, row, q, v);
    }
}

// ---------------- degree count: 4 edges per thread ----------------
__global__ void k_count_deg(const int* __restrict__ row) {
    int e4 = blockIdx.x * blockDim.x + threadIdx.x;
    if (e4 < NE / 4) {
        int4 r = __ldg((const int4*)row + e4);
        atomicAdd(&g_deg[r.x], 1);
        atomicAdd(&g_deg[r.y], 1);
        atomicAdd(&g_deg[r.z], 1);
        atomicAdd(&g_deg[r.w], 1);
    }
}

// ---------------- scan: A (block sums via shfl reduce), C (shfl scans + write out) ----------------
__global__ void __launch_bounds__(256) k_scanA() {
    __shared__ int sw[8];
    int t = threadIdx.x;
    int lane = t & 31, wid = t >> 5;
    int i = blockIdx.x * 256 + t;
    int v = (i < NN) ? g_deg[i] : 0;
#pragma unroll
    for (int o = 16; o > 0; o >>= 1) v += __shfl_down_sync(0xffffffffu, v, o);
    if (lane == 0) sw[wid] = v;
    __syncthreads();
    if (t == 0) {
        int s = 0;
#pragma unroll
        for (int k = 0; k < 8; k++) s += sw[k];
        g_bsum[blockIdx.x] = s;
    }
}
// inclusive 256-scan via shfl
__device__ __forceinline__ int scan256(int x, int lane, int wid, int* sw) {
#pragma unroll
    for (int o = 1; o < 32; o <<= 1) {
        int u = __shfl_up_sync(0xffffffffu, x, o);
        if (lane >= o) x += u;
    }
    if (lane == 31) sw[wid] = x;
    __syncthreads();
    if (wid == 0) {
        int y = (lane < 8) ? sw[lane] : 0;
#pragma unroll
        for (int o = 1; o < 8; o <<= 1) {
            int u = __shfl_up_sync(0xffffffffu, y, o);
            if (lane >= o) y += u;
        }
        if (lane < 8) sw[lane] = y;
    }
    __syncthreads();
    if (wid > 0) x += sw[wid - 1];
    return x;
}
__global__ void __launch_bounds__(256) k_scanC() {
    __shared__ int sw1[8];
    __shared__ int sw2[8];
    __shared__ int sBoff[256];
    int t = threadIdx.x;
    int lane = t & 31, wid = t >> 5;
    int bs = (t < NB) ? g_bsum[t] : 0;
    int bsInc = scan256(bs, lane, wid, sw1);
    sBoff[t] = bsInc;
    __syncthreads();
    int blockOff = (blockIdx.x == 0) ? 0 : sBoff[blockIdx.x - 1];
    int i = blockIdx.x * 256 + t;
    int dg = (i < NN) ? g_deg[i] : 0;
    int dgInc = scan256(dg, lane, wid, sw2);
    int off = blockOff + dgInc - dg;   // exclusive
    if (i < NN) {
        g_rowptr[i] = off;
        g_cursor[i] = off;
        g_invdeg[i] = 1.0f / fmaxf((float)dg, 1.0f);
        if (i == NN - 1) g_rowptr[NN] = off + dg;
    }
}

// ---------------- fill: 4 edges per thread ----------------
__global__ void k_fill(const int* __restrict__ row, const int* __restrict__ col) {
    int e4 = blockIdx.x * blockDim.x + threadIdx.x;
    if (e4 < NE / 4) {
        int4 r = __ldg((const int4*)row + e4);
        int4 c = __ldg((const int4*)col + e4);
        g_csr_col[atomicAdd(&g_cursor[r.x], 1)] = c.x;
        g_csr_col[atomicAdd(&g_cursor[r.y], 1)] = c.y;
        g_csr_col[atomicAdd(&g_cursor[r.z], 1)] = c.z;
        g_csr_col[atomicAdd(&g_cursor[r.w], 1)] = c.w;
    }
}

// ---------------- gather: agg planes = split(invdeg[n] * sum_nbr maybe_relu(src[c])) ----------------
#define RELU4(v)                                                  \
    do {                                                          \
        (v).x = fmaxf((v).x, 0.f); (v).y = fmaxf((v).y, 0.f);     \
        (v).z = fmaxf((v).z, 0.f); (v).w = fmaxf((v).w, 0.f);     \
    } while (0)
#define ACC4(a, v)                                                \
    do {                                                          \
        (a).x += (v).x; (a).y += (v).y;                           \
        (a).z += (v).z; (a).w += (v).w;                           \
    } while (0)

template <bool RELU>
__global__ void __launch_bounds__(256) k_gather(const float* __restrict__ src) {
    int w    = (blockIdx.x * blockDim.x + threadIdx.x) >> 5;
    int lane = threadIdx.x & 31;
    if (w >= NN) return;
    const int beg = g_rowptr[w];
    const int end = g_rowptr[w + 1];

    float4 a0 = make_float4(0.f, 0.f, 0.f, 0.f);
    float4 a1 = a0, a2 = a0, a3 = a0;
    int i = beg;
    for (; i + 7 < end; i += 8) {
        int c0 = __ldg(g_csr_col + i);
        int c1 = __ldg(g_csr_col + i + 1);
        int c2 = __ldg(g_csr_col + i + 2);
        int c3 = __ldg(g_csr_col + i + 3);
        int c4 = __ldg(g_csr_col + i + 4);
        int c5 = __ldg(g_csr_col + i + 5);
        int c6 = __ldg(g_csr_col + i + 6);
        int c7 = __ldg(g_csr_col + i + 7);
        float4 v0 = __ldg((const float4*)(src + (size_t)c0 * DD) + lane);
        float4 v1 = __ldg((const float4*)(src + (size_t)c1 * DD) + lane);
        float4 v2 = __ldg((const float4*)(src + (size_t)c2 * DD) + lane);
        float4 v3 = __ldg((const float4*)(src + (size_t)c3 * DD) + lane);
        float4 v4 = __ldg((const float4*)(src + (size_t)c4 * DD) + lane);
        float4 v5 = __ldg((const float4*)(src + (size_t)c5 * DD) + lane);
        float4 v6 = __ldg((const float4*)(src + (size_t)c6 * DD) + lane);
        float4 v7 = __ldg((const float4*)(src + (size_t)c7 * DD) + lane);
        if (RELU) {
            RELU4(v0); RELU4(v1); RELU4(v2); RELU4(v3);
            RELU4(v4); RELU4(v5); RELU4(v6); RELU4(v7);
        }
        ACC4(a0, v0); ACC4(a1, v1); ACC4(a2, v2); ACC4(a3, v3);
        ACC4(a0, v4); ACC4(a1, v5); ACC4(a2, v6); ACC4(a3, v7);
    }
    for (; i + 3 < end; i += 4) {
        int c0 = __ldg(g_csr_col + i);
        int c1 = __ldg(g_csr_col + i + 1);
        int c2 = __ldg(g_csr_col + i + 2);
        int c3 = __ldg(g_csr_col + i + 3);
        float4 v0 = __ldg((const float4*)(src + (size_t)c0 * DD) + lane);
        float4 v1 = __ldg((const float4*)(src + (size_t)c1 * DD) + lane);
        float4 v2 = __ldg((const float4*)(src + (size_t)c2 * DD) + lane);
        float4 v3 = __ldg((const float4*)(src + (size_t)c3 * DD) + lane);
        if (RELU) { RELU4(v0); RELU4(v1); RELU4(v2); RELU4(v3); }
        ACC4(a0, v0); ACC4(a1, v1); ACC4(a2, v2); ACC4(a3, v3);
    }
    for (; i < end; i++) {
        int c0 = __ldg(g_csr_col + i);
        float4 v0 = __ldg((const float4*)(src + (size_t)c0 * DD) + lane);
        if (RELU) RELU4(v0);
        ACC4(a0, v0);
    }

    float s = g_invdeg[w];
    float4 acc;
    acc.x = ((a0.x + a1.x) + (a2.x + a3.x)) * s;
    acc.y = ((a0.y + a1.y) + (a2.y + a3.y)) * s;
    acc.z = ((a0.z + a1.z) + (a2.z + a3.z)) * s;
    acc.w = ((a0.w + a1.w) + (a2.w + a3.w)) * s;

    // split + swizzled store into agg tile-planes
    int tile  = w >> 7;
    int rowt  = w & 127;
    int chunk = lane >> 4;      // k-half
    int q     = lane & 15;
    char* hb = (char*)g_aggh4 + (size_t)(chunk * NTILES + tile) * 16384;
    char* lb = (char*)g_aggl4 + (size_t)(chunk * NTILES + tile) * 16384;
    st_hl(hb, lb, rowt, q, acc);
}

// ================= persistent mma.sync bf16-split GEMM (pipelined fill) =================
// Grid 148, 1 CTA/SM, 256 threads. W planes (128KB) resident in smem;
// A-chunk fills register-prefetched. mma issue order: pass-outer so consecutive
// HMMAs target distinct accumulators (dep distance 4, not 1).

#define OFF_BIAS 0
#define OFF_B    1024                       // 8 planes x 16KB
#define OFF_AHI  (1024 + 131072)
#define OFF_ALO  (1024 + 131072 + 16384)
#define SMEM_GEMM (1024 + 131072 + 32768)   // 164864

__device__ __forceinline__ uint32_t s2u(const void* p) {
    uint32_t a;
    asm("{ .reg .u64 t; cvta.to.shared.u64 t, %1; cvt.u32.u64 %0, t; }" : "=r"(a) : "l"(p));
    return a;
}
__device__ __forceinline__ void ldsm4(uint32_t& r0, uint32_t& r1, uint32_t& r2, uint32_t& r3,
                                      uint32_t addr) {
    asm volatile("ldmatrix.sync.aligned.m8n8.x4.shared.b16 {%0,%1,%2,%3}, [%4];"
                 : "=r"(r0), "=r"(r1), "=r"(r2), "=r"(r3) : "r"(addr));
}
__device__ __forceinline__ void mma16816(float* d, const uint32_t* a, const uint32_t* b) {
    asm volatile("mma.sync.aligned.m16n8k16.row.col.f32.bf16.bf16.f32 "
                 "{%0,%1,%2,%3}, {%4,%5,%6,%7}, {%8,%9}, {%0,%1,%2,%3};"
                 : "+f"(d[0]), "+f"(d[1]), "+f"(d[2]), "+f"(d[3])
                 : "r"(a[0]), "r"(a[1]), "r"(a[2]), "r"(a[3]), "r"(b[0]), "r"(b[1]));
}
__device__ __forceinline__ uint32_t tile_addr(uint32_t planeBase, int lane, int r0, int k0) {
    int rr = r0 + (lane & 15);
    int kk = k0 + ((lane >> 4) << 3);
    uint32_t off = rr * 128 + kk * 2;
    return planeBase + (off ^ ((off >> 3) & 0x70));
}

// prefetch agg chunk (c<2) of a tile into 8 uint4 regs
__device__ __forceinline__ void pf_agg(uint4* pf, int c, int tile, int t) {
    const uint4* ah = g_aggh4 + (size_t)(c * NTILES + tile) * 1024;
    const uint4* al = g_aggl4 + (size_t)(c * NTILES + tile) * 1024;
#pragma unroll
    for (int u = 0; u < 4; u++) {
        pf[u]     = __ldg(ah + t + u * 256);
        pf[4 + u] = __ldg(al + t + u * 256);
    }
}
// prefetch fp32 h half (0/1) of a tile into 8 float4 regs (as uint4)
__device__ __forceinline__ void pf_h(uint4* pf, const float* h, int half, int rowBase, int t) {
#pragma unroll
    for (int u = 0; u < 8; u++) {
        int idx = t + u * 256;
        int row = idx >> 4, q = idx & 15;
        int gi = rowBase + row;
        float4 va = make_float4(0.f, 0.f, 0.f, 0.f);
        if (gi < NN)
            va = __ldg((const float4*)(h + (size_t)gi * DD + half * 64) + q);
        pf[u] = *(uint4*)&va;
    }
}

template <bool RELU, bool RES>
__global__ void __launch_bounds__(256)
k_gemm_mma(const float* __restrict__ h, int layer, const float* __restrict__ bias,
           float* __restrict__ out)
{
    extern __shared__ char smem[];
    const uint32_t sb = s2u(smem);
    const int t    = threadIdx.x;
    const int wid  = t >> 5;
    const int lane = t & 31;
    const int wm = (wid >> 2) * 64;
    const int wn = (wid & 3) * 32;

    if (t < 128) ((float*)(smem + OFF_BIAS))[t] = bias[t];

    // ---- load ALL W planes once: 8192 uint4 ----
    {
        uint4* sB = (uint4*)(smem + OFF_B);
#pragma unroll
        for (int u = 0; u < 32; u++) {
            int idx = t + u * 256;          // 0..8191
            int p   = idx >> 10;            // plane 0..7
            int r   = idx & 1023;
            int c   = p >> 1;
            const uint4* src = (p & 1) ? (g_wl4 + (size_t)(layer * 4 + c) * 1024)
                                       : (g_wh4 + (size_t)(layer * 4 + c) * 1024);
            sB[idx] = __ldg(src + r);
        }
    }

    uint4* sAh = (uint4*)(smem + OFF_AHI);
    uint4* sAl = (uint4*)(smem + OFF_ALO);
    const float* bsh = (const float*)(smem + OFF_BIAS);
    const int tr = lane >> 2;
    const int tc = (lane & 3) * 2;

    uint4 pf[8];
    if (blockIdx.x < NTILES) pf_agg(pf, 0, blockIdx.x, t);

    for (int tile = blockIdx.x; tile < NTILES; tile += GRID_GEMM) {
        const int rowBase = tile * 128;
        float acc[4][4][4];
#pragma unroll
        for (int i = 0; i < 4; i++)
#pragma unroll
            for (int j = 0; j < 4; j++)
#pragma unroll
                for (int q = 0; q < 4; q++) acc[i][j][q] = 0.f;

        for (int c = 0; c < 4; c++) {
            __syncthreads();   // previous chunk's mma (or prev tile epilogue) done
            // ---- store prefetched chunk c into A planes ----
            if (c < 2) {
#pragma unroll
                for (int u = 0; u < 4; u++) {
                    sAh[t + u * 256] = pf[u];
                    sAl[t + u * 256] = pf[4 + u];
                }
            } else {
#pragma unroll
                for (int u = 0; u < 8; u++) {
                    int idx = t + u * 256;
                    int row = idx >> 4, q = idx & 15;
                    float4 va = *(float4*)&pf[u];
                    if (RELU) RELU4(va);
                    st_hl(smem + OFF_AHI, smem + OFF_ALO, row, q, va);
                }
            }
            __syncthreads();
            // ---- issue prefetch for next chunk (overlaps with mma below) ----
            if (c == 0) {
                pf_agg(pf, 1, tile, t);
            } else if (c < 3) {
                pf_h(pf, h, c - 1, rowBase, t);   // c=1 -> half0 (chunk2), c=2 -> half1 (chunk3)
            } else {
                int ntile = tile + GRID_GEMM;
                if (ntile < NTILES) pf_agg(pf, 0, ntile, t);
            }

            const uint32_t bHiBase = sb + OFF_B + c * 32768;
            const uint32_t bLoBase = bHiBase + 16384;
#pragma unroll
            for (int ks = 0; ks < 4; ks++) {
                const int k0 = ks * 16;
                uint32_t bhi[4][2], blo[4][2];
#pragma unroll
                for (int p = 0; p < 2; p++) {
                    uint32_t r0, r1, r2, r3;
                    ldsm4(r0, r1, r2, r3, tile_addr(bHiBase, lane, wn + p * 16, k0));
                    bhi[2 * p][0] = r0;     bhi[2 * p][1] = r2;
                    bhi[2 * p + 1][0] = r1; bhi[2 * p + 1][1] = r3;
                    ldsm4(r0, r1, r2, r3, tile_addr(bLoBase, lane, wn + p * 16, k0));
                    blo[2 * p][0] = r0;     blo[2 * p][1] = r2;
                    blo[2 * p + 1][0] = r1; blo[2 * p + 1][1] = r3;
                }
#pragma unroll
                for (int i = 0; i < 4; i++) {
                    uint32_t ahi[4], alo[4];
                    ldsm4(ahi[0], ahi[1], ahi[2], ahi[3],
                          tile_addr(sb + OFF_AHI, lane, wm + i * 16, k0));
                    ldsm4(alo[0], alo[1], alo[2], alo[3],
                          tile_addr(sb + OFF_ALO, lane, wm + i * 16, k0));
                    // pass-outer, j-inner: consecutive mmas hit distinct acc tiles
#pragma unroll
                    for (int j = 0; j < 4; j++) mma16816(acc[i][j], ahi, bhi[j]);
#pragma unroll
                    for (int j = 0; j < 4; j++) mma16816(acc[i][j], ahi, blo[j]);
#pragma unroll
                    for (int j = 0; j < 4; j++) mma16816(acc[i][j], alo, bhi[j]);
                }
            }
        }

        // ---- epilogue: bias (+ residual), direct register->gmem ----
#pragma unroll
        for (int i = 0; i < 4; i++) {
#pragma unroll
            for (int half = 0; half < 2; half++) {
                int gi = rowBase + wm + i * 16 + tr + half * 8;
                if (gi >= NN) continue;
#pragma unroll
                for (int j = 0; j < 4; j++) {
                    int col = wn + j * 8 + tc;
                    float2 o;
                    o.x = acc[i][j][half * 2]     + bsh[col];
                    o.y = acc[i][j][half * 2 + 1] + bsh[col + 1];
                    if (RES) {
                        float2 rv = __ldg((const float2*)(h + (size_t)gi * DD + col));
                        o.x += rv.x; o.y += rv.y;
                    }
                    *(float2*)(out + (size_t)gi * DD + col) = o;
                }
            }
        }
    }
}

// ---------------- launch ----------------
extern "C" void kernel_launch(void* const* d_in, const int* in_sizes, int n_in,
                              void* d_out, int out_size) {
    const float* x    = (const float*)d_in[0];
    const int*   erow = (const int*)  d_in[1];
    const int*   ecol = (const int*)  d_in[2];
    const float* Wl0 = (const float*)d_in[3];
    const float* Wr0 = (const float*)d_in[4];
    const float* b0  = (const float*)d_in[5];
    const float* Wl1 = (const float*)d_in[6];
    const float* Wr1 = (const float*)d_in[7];
    const float* b1  = (const float*)d_in[8];
    const float* Wl2 = (const float*)d_in[9];
    const float* Wr2 = (const float*)d_in[10];
    const float* b2  = (const float*)d_in[11];
    float* out = (float*)d_out;

    float *p_x1 = nullptr, *p_x2 = nullptr;
    cudaGetSymbolAddress((void**)&p_x1, g_x1);
    cudaGetSymbolAddress((void**)&p_x2, g_x2);

    cudaFuncSetAttribute(k_gemm_mma<false, false>,
                         cudaFuncAttributeMaxDynamicSharedMemorySize, SMEM_GEMM);
    cudaFuncSetAttribute(k_gemm_mma<true, true>,
                         cudaFuncAttributeMaxDynamicSharedMemorySize, SMEM_GEMM);

    const int edge4Blocks  = (NE / 4 + 255) / 256;      // 782
    const int gatherBlocks = (NN * 32 + 255) / 256;     // 6250

    // setup (zero deg + W pre-split, fused) then CSR build
    k_setup<<<NB + 96, 256>>>(Wl0, Wr0, Wl1, Wr1, Wl2, Wr2);
    k_count_deg<<<edge4Blocks, 256>>>(erow);
    k_scanA<<<NB, 256>>>();
    k_scanC<<<NB, 256>>>();
    k_fill<<<edge4Blocks, 256>>>(erow, ecol);

    // ---- layer 0: x1 = sage(x) ----
    k_gather<false><<<gatherBlocks, 256>>>(x);
    k_gemm_mma<false, false><<<GRID_GEMM, 256, SMEM_GEMM>>>(x, 0, b0, p_x1);

    // ---- layer 1: x2 = sage(relu(x1)) + x1 ----
    k_gather<true><<<gatherBlocks, 256>>>(p_x1);
    k_gemm_mma<true, true><<<GRID_GEMM, 256, SMEM_GEMM>>>(p_x1, 1, b1, p_x2);

    // ---- layer 2: out = sage(relu(x2)) + x2 ----
    k_gather<true><<<gatherBlocks, 256>>>(p_x2);
    k_gemm_mma<true, true><<<GRID_GEMM, 256, SMEM_GEMM>>>(p_x2, 2, b2, out);
}

// round 16
// speedup vs baseline: 1.0669x; 1.0047x over previous
#include <cuda_runtime.h>
#include <cuda_bf16.h>
#include <cstdint>

#define NN 50000
#define NE 800000
#define DD 128
#define NTILES 391    // ceil(NN/128)
#define NB 196        // ceil(NN/256)
#define GRID_GEMM 148

// Scratch (static __device__ arrays: allocation-free)
static __device__ float g_x1 [(size_t)NN * DD];
static __device__ float g_x2 [(size_t)NN * DD];
static __device__ float g_invdeg[NN];
static __device__ int   g_deg[NN];
static __device__ int   g_rowptr[NN + 1];
static __device__ int   g_cursor[NN];
static __device__ int   g_csr_col[NE];
static __device__ int   g_bsum[NB];
// bf16 hi/lo planes, pre-swizzled 16KB tile-planes (128 rows x 128B)
static __device__ uint4 g_aggh4[2 * NTILES * 1024];   // agg chunks 0-1
static __device__ uint4 g_aggl4[2 * NTILES * 1024];
static __device__ uint4 g_wh4[12 * 1024];             // 3 layers x 4 chunks
static __device__ uint4 g_wl4[12 * 1024];

// split one float4 into bf16 hi/lo, swizzled 8B stores at (row, q)
__device__ __forceinline__ void st_hl(char* hiBase, char* loBase, int row, int q, float4 v) {
    __nv_bfloat16 hx = __float2bfloat16_rn(v.x);
    __nv_bfloat16 hy = __float2bfloat16_rn(v.y);
    __nv_bfloat16 hz = __float2bfloat16_rn(v.z);
    __nv_bfloat16 hw = __float2bfloat16_rn(v.w);
    __nv_bfloat16 lx = __float2bfloat16_rn(v.x - __bfloat162float(hx));
    __nv_bfloat16 ly = __float2bfloat16_rn(v.y - __bfloat162float(hy));
    __nv_bfloat16 lz = __float2bfloat16_rn(v.z - __bfloat162float(hz));
    __nv_bfloat16 lw = __float2bfloat16_rn(v.w - __bfloat162float(hw));
    __nv_bfloat162 H01, H23, L01, L23;
    H01.x = hx; H01.y = hy; H23.x = hz; H23.y = hw;
    L01.x = lx; L01.y = ly; L23.x = lz; L23.y = lw;
    int off = row * 128 + q * 8;
    int sw = off ^ ((off >> 3) & 0x70);
    uint2 Hw, Lw;
    Hw.x = *(uint32_t*)&H01; Hw.y = *(uint32_t*)&H23;
    Lw.x = *(uint32_t*)&L01; Lw.y = *(uint32_t*)&L23;
    *(uint2*)(hiBase + sw) = Hw;
    *(uint2*)(loBase + sw) = Lw;
}

// ---------------- fused setup: zero deg (blocks 0..195) + pre-split W (blocks 196..291) ----------------
__global__ void k_setup(const float* __restrict__ Wl0, const float* __restrict__ Wr0,
                        const float* __restrict__ Wl1, const float* __restrict__ Wr1,
                        const float* __restrict__ Wl2, const float* __restrict__ Wr2) {
    int b = blockIdx.x;
    int t = threadIdx.x;
    if (b < NB) {
        int i = b * 256 + t;
        if (i < NN) g_deg[i] = 0;
    } else {
        int idx = (b - NB) * 256 + t;      // 0..24575 (3 layers x 8192)
        int layer = idx >> 13;
        int rem13 = idx & 8191;
        int w     = rem13 >> 12;           // 0: Wl, 1: Wr
        int rem   = rem13 & 4095;
        int row   = rem >> 5;              // out-dim 0..127
        int slot  = rem & 31;              // float4 slot across 128 in-dims
        int chunk = w * 2 + (slot >> 4);
        int q     = slot & 15;
        const float* W = (layer == 0) ? (w ? Wr0 : Wl0)
                       : (layer == 1) ? (w ? Wr1 : Wl1)
                                      : (w ? Wr2 : Wl2);
        float4 v = __ldg((const float4*)(W + (size_t)row * DD) + slot);
        char* hb = (char*)g_wh4 + (size_t)(layer * 4 + chunk) * 16384;
        char* lb = (char*)g_wl4 + (size_t)(layer * 4 + chunk) * 16384;
        st_hl(hb, lb, row, q, v);
    }
}

// ---------------- degree count: 4 edges per thread ----------------
__global__ void k_count_deg(const int* __restrict__ row) {
    int e4 = blockIdx.x * blockDim.x + threadIdx.x;
    if (e4 < NE / 4) {
        int4 r = __ldg((const int4*)row + e4);
        atomicAdd(&g_deg[r.x], 1);
        atomicAdd(&g_deg[r.y], 1);
        atomicAdd(&g_deg[r.z], 1);
        atomicAdd(&g_deg[r.w], 1);
    }
}

// ---------------- scan: A (block sums via shfl reduce), C (shfl scans + write out) ----------------
__global__ void __launch_bounds__(256) k_scanA() {
    __shared__ int sw[8];
    int t = threadIdx.x;
    int lane = t & 31, wid = t >> 5;
    int i = blockIdx.x * 256 + t;
    int v = (i < NN) ? g_deg[i] : 0;
#pragma unroll
    for (int o = 16; o > 0; o >>= 1) v += __shfl_down_sync(0xffffffffu, v, o);
    if (lane == 0) sw[wid] = v;
    __syncthreads();
    if (t == 0) {
        int s = 0;
#pragma unroll
        for (int k = 0; k < 8; k++) s += sw[k];
        g_bsum[blockIdx.x] = s;
    }
}
// inclusive 256-scan via shfl
__device__ __forceinline__ int scan256(int x, int lane, int wid, int* sw) {
#pragma unroll
    for (int o = 1; o < 32; o <<= 1) {
        int u = __shfl_up_sync(0xffffffffu, x, o);
        if (lane >= o) x += u;
    }
    if (lane == 31) sw[wid] = x;
    __syncthreads();
    if (wid == 0) {
        int y = (lane < 8) ? sw[lane] : 0;
#pragma unroll
        for (int o = 1; o < 8; o <<= 1) {
            int u = __shfl_up_sync(0xffffffffu, y, o);
            if (lane >= o) y += u;
        }
        if (lane < 8) sw[lane] = y;
    }
    __syncthreads();
    if (wid > 0) x += sw[wid - 1];
    return x;
}
__global__ void __launch_bounds__(256) k_scanC() {
    __shared__ int sw1[8];
    __shared__ int sw2[8];
    __shared__ int sBoff[256];
    int t = threadIdx.x;
    int lane = t & 31, wid = t >> 5;
    int bs = (t < NB) ? g_bsum[t] : 0;
    int bsInc = scan256(bs, lane, wid, sw1);
    sBoff[t] = bsInc;
    __syncthreads();
    int blockOff = (blockIdx.x == 0) ? 0 : sBoff[blockIdx.x - 1];
    int i = blockIdx.x * 256 + t;
    int dg = (i < NN) ? g_deg[i] : 0;
    int dgInc = scan256(dg, lane, wid, sw2);
    int off = blockOff + dgInc - dg;   // exclusive
    if (i < NN) {
        g_rowptr[i] = off;
        g_cursor[i] = off;
        g_invdeg[i] = 1.0f / fmaxf((float)dg, 1.0f);
        if (i == NN - 1) g_rowptr[NN] = off + dg;
    }
}

// ---------------- fill: 4 edges per thread ----------------
__global__ void k_fill(const int* __restrict__ row, const int* __restrict__ col) {
    int e4 = blockIdx.x * blockDim.x + threadIdx.x;
    if (e4 < NE / 4) {
        int4 r = __ldg((const int4*)row + e4);
        int4 c = __ldg((const int4*)col + e4);
        g_csr_col[atomicAdd(&g_cursor[r.x], 1)] = c.x;
        g_csr_col[atomicAdd(&g_cursor[r.y], 1)] = c.y;
        g_csr_col[atomicAdd(&g_cursor[r.z], 1)] = c.z;
        g_csr_col[atomicAdd(&g_cursor[r.w], 1)] = c.w;
    }
}

// ---------------- gather: agg planes = split(invdeg[n] * sum_nbr maybe_relu(src[c])) ----------------
#define RELU4(v)                                                  \
    do {                                                          \
        (v).x = fmaxf((v).x, 0.f); (v).y = fmaxf((v).y, 0.f);     \
        (v).z = fmaxf((v).z, 0.f); (v).w = fmaxf((v).w, 0.f);     \
    } while (0)
#define ACC4(a, v)                                                \
    do {                                                          \
        (a).x += (v).x; (a).y += (v).y;                           \
        (a).z += (v).z; (a).w += (v).w;                           \
    } while (0)

template <bool RELU>
__global__ void __launch_bounds__(256) k_gather(const float* __restrict__ src) {
    int w    = (blockIdx.x * blockDim.x + threadIdx.x) >> 5;
    int lane = threadIdx.x & 31;
    if (w >= NN) return;
    const int beg = g_rowptr[w];
    const int end = g_rowptr[w + 1];

    float4 a0 = make_float4(0.f, 0.f, 0.f, 0.f);
    float4 a1 = a0, a2 = a0, a3 = a0;
    int i = beg;
    for (; i + 7 < end; i += 8) {
        int c0 = __ldg(g_csr_col + i);
        int c1 = __ldg(g_csr_col + i + 1);
        int c2 = __ldg(g_csr_col + i + 2);
        int c3 = __ldg(g_csr_col + i + 3);
        int c4 = __ldg(g_csr_col + i + 4);
        int c5 = __ldg(g_csr_col + i + 5);
        int c6 = __ldg(g_csr_col + i + 6);
        int c7 = __ldg(g_csr_col + i + 7);
        float4 v0 = __ldg((const float4*)(src + (size_t)c0 * DD) + lane);
        float4 v1 = __ldg((const float4*)(src + (size_t)c1 * DD) + lane);
        float4 v2 = __ldg((const float4*)(src + (size_t)c2 * DD) + lane);
        float4 v3 = __ldg((const float4*)(src + (size_t)c3 * DD) + lane);
        float4 v4 = __ldg((const float4*)(src + (size_t)c4 * DD) + lane);
        float4 v5 = __ldg((const float4*)(src + (size_t)c5 * DD) + lane);
        float4 v6 = __ldg((const float4*)(src + (size_t)c6 * DD) + lane);
        float4 v7 = __ldg((const float4*)(src + (size_t)c7 * DD) + lane);
        if (RELU) {
            RELU4(v0); RELU4(v1); RELU4(v2); RELU4(v3);
            RELU4(v4); RELU4(v5); RELU4(v6); RELU4(v7);
        }
        ACC4(a0, v0); ACC4(a1, v1); ACC4(a2, v2); ACC4(a3, v3);
        ACC4(a0, v4); ACC4(a1, v5); ACC4(a2, v6); ACC4(a3, v7);
    }
    for (; i + 3 < end; i += 4) {
        int c0 = __ldg(g_csr_col + i);
        int c1 = __ldg(g_csr_col + i + 1);
        int c2 = __ldg(g_csr_col + i + 2);
        int c3 = __ldg(g_csr_col + i + 3);
        float4 v0 = __ldg((const float4*)(src + (size_t)c0 * DD) + lane);
        float4 v1 = __ldg((const float4*)(src + (size_t)c1 * DD) + lane);
        float4 v2 = __ldg((const float4*)(src + (size_t)c2 * DD) + lane);
        float4 v3 = __ldg((const float4*)(src + (size_t)c3 * DD) + lane);
        if (RELU) { RELU4(v0); RELU4(v1); RELU4(v2); RELU4(v3); }
        ACC4(a0, v0); ACC4(a1, v1); ACC4(a2, v2); ACC4(a3, v3);
    }
    for (; i < end; i++) {
        int c0 = __ldg(g_csr_col + i);
        float4 v0 = __ldg((const float4*)(src + (size_t)c0 * DD) + lane);
        if (RELU) RELU4(v0);
        ACC4(a0, v0);
    }

    float s = g_invdeg[w];
    float4 acc;
    acc.x = ((a0.x + a1.x) + (a2.x + a3.x)) * s;
    acc.y = ((a0.y + a1.y) + (a2.y + a3.y)) * s;
    acc.z = ((a0.z + a1.z) + (a2.z + a3.z)) * s;
    acc.w = ((a0.w + a1.w) + (a2.w + a3.w)) * s;

    // split + swizzled store into agg tile-planes
    int tile  = w >> 7;
    int rowt  = w & 127;
    int chunk = lane >> 4;      // k-half
    int q     = lane & 15;
    char* hb = (char*)g_aggh4 + (size_t)(chunk * NTILES + tile) * 16384;
    char* lb = (char*)g_aggl4 + (size_t)(chunk * NTILES + tile) * 16384;
    st_hl(hb, lb, rowt, q, acc);
}

// ================= persistent mma.sync bf16-split GEMM (pipelined fill + frags) =================
// Grid 148, 1 CTA/SM, 256 threads. W planes (128KB) resident in smem;
// A-chunk fills register-prefetched; A-FRAGMENT ldsm double-buffered so the
// shared-load latency hides behind the 12 mmas of the previous m-tile.

#define OFF_BIAS 0
#define OFF_B    1024                       // 8 planes x 16KB
#define OFF_AHI  (1024 + 131072)
#define OFF_ALO  (1024 + 131072 + 16384)
#define SMEM_GEMM (1024 + 131072 + 32768)   // 164864

__device__ __forceinline__ uint32_t s2u(const void* p) {
    uint32_t a;
    asm("{ .reg .u64 t; cvta.to.shared.u64 t, %1; cvt.u32.u64 %0, t; }" : "=r"(a) : "l"(p));
    return a;
}
__device__ __forceinline__ void ldsm4(uint32_t& r0, uint32_t& r1, uint32_t& r2, uint32_t& r3,
                                      uint32_t addr) {
    asm volatile("ldmatrix.sync.aligned.m8n8.x4.shared.b16 {%0,%1,%2,%3}, [%4];"
                 : "=r"(r0), "=r"(r1), "=r"(r2), "=r"(r3) : "r"(addr));
}
__device__ __forceinline__ void mma16816(float* d, const uint32_t* a, const uint32_t* b) {
    asm volatile("mma.sync.aligned.m16n8k16.row.col.f32.bf16.bf16.f32 "
                 "{%0,%1,%2,%3}, {%4,%5,%6,%7}, {%8,%9}, {%0,%1,%2,%3};"
                 : "+f"(d[0]), "+f"(d[1]), "+f"(d[2]), "+f"(d[3])
                 : "r"(a[0]), "r"(a[1]), "r"(a[2]), "r"(a[3]), "r"(b[0]), "r"(b[1]));
}
__device__ __forceinline__ uint32_t tile_addr(uint32_t planeBase, int lane, int r0, int k0) {
    int rr = r0 + (lane & 15);
    int kk = k0 + ((lane >> 4) << 3);
    uint32_t off = rr * 128 + kk * 2;
    return planeBase + (off ^ ((off >> 3) & 0x70));
}

// prefetch agg chunk (c<2) of a tile into 8 uint4 regs
__device__ __forceinline__ void pf_agg(uint4* pf, int c, int tile, int t) {
    const uint4* ah = g_aggh4 + (size_t)(c * NTILES + tile) * 1024;
    const uint4* al = g_aggl4 + (size_t)(c * NTILES + tile) * 1024;
#pragma unroll
    for (int u = 0; u < 4; u++) {
        pf[u]     = __ldg(ah + t + u * 256);
        pf[4 + u] = __ldg(al + t + u * 256);
    }
}
// prefetch fp32 h half (0/1) of a tile into 8 float4 regs (as uint4)
__device__ __forceinline__ void pf_h(uint4* pf, const float* h, int half, int rowBase, int t) {
#pragma unroll
    for (int u = 0; u < 8; u++) {
        int idx = t + u * 256;
        int row = idx >> 4, q = idx & 15;
        int gi = rowBase + row;
        float4 va = make_float4(0.f, 0.f, 0.f, 0.f);
        if (gi < NN)
            va = __ldg((const float4*)(h + (size_t)gi * DD + half * 64) + q);
        pf[u] = *(uint4*)&va;
    }
}

template <bool RELU, bool RES>
__global__ void __launch_bounds__(256)
k_gemm_mma(const float* __restrict__ h, int layer, const float* __restrict__ bias,
           float* __restrict__ out)
{
    extern __shared__ char smem[];
    const uint32_t sb = s2u(smem);
    const int t    = threadIdx.x;
    const int wid  = t >> 5;
    const int lane = t & 31;
    const int wm = (wid >> 2) * 64;
    const int wn = (wid & 3) * 32;

    if (t < 128) ((float*)(smem + OFF_BIAS))[t] = bias[t];

    // ---- load ALL W planes once: 8192 uint4 ----
    {
        uint4* sB = (uint4*)(smem + OFF_B);
#pragma unroll
        for (int u = 0; u < 32; u++) {
            int idx = t + u * 256;          // 0..8191
            int p   = idx >> 10;            // plane 0..7
            int r   = idx & 1023;
            int c   = p >> 1;
            const uint4* src = (p & 1) ? (g_wl4 + (size_t)(layer * 4 + c) * 1024)
                                       : (g_wh4 + (size_t)(layer * 4 + c) * 1024);
            sB[idx] = __ldg(src + r);
        }
    }

    uint4* sAh = (uint4*)(smem + OFF_AHI);
    uint4* sAl = (uint4*)(smem + OFF_ALO);
    const float* bsh = (const float*)(smem + OFF_BIAS);
    const int tr = lane >> 2;
    const int tc = (lane & 3) * 2;

    uint4 pf[8];
    if (blockIdx.x < NTILES) pf_agg(pf, 0, blockIdx.x, t);

    for (int tile = blockIdx.x; tile < NTILES; tile += GRID_GEMM) {
        const int rowBase = tile * 128;
        float acc[4][4][4];
#pragma unroll
        for (int i = 0; i < 4; i++)
#pragma unroll
            for (int j = 0; j < 4; j++)
#pragma unroll
                for (int q = 0; q < 4; q++) acc[i][j][q] = 0.f;

        for (int c = 0; c < 4; c++) {
            __syncthreads();   // previous chunk's mma (or prev tile epilogue) done
            // ---- store prefetched chunk c into A planes ----
            if (c < 2) {
#pragma unroll
                for (int u = 0; u < 4; u++) {
                    sAh[t + u * 256] = pf[u];
                    sAl[t + u * 256] = pf[4 + u];
                }
            } else {
#pragma unroll
                for (int u = 0; u < 8; u++) {
                    int idx = t + u * 256;
                    int row = idx >> 4, q = idx & 15;
                    float4 va = *(float4*)&pf[u];
                    if (RELU) RELU4(va);
                    st_hl(smem + OFF_AHI, smem + OFF_ALO, row, q, va);
                }
            }
            __syncthreads();
            // ---- issue prefetch for next chunk (overlaps with mma below) ----
            if (c == 0) {
                pf_agg(pf, 1, tile, t);
            } else if (c < 3) {
                pf_h(pf, h, c - 1, rowBase, t);   // c=1 -> half0 (chunk2), c=2 -> half1 (chunk3)
            } else {
                int ntile = tile + GRID_GEMM;
                if (ntile < NTILES) pf_agg(pf, 0, ntile, t);
            }

            const uint32_t bHiBase = sb + OFF_B + c * 32768;
            const uint32_t bLoBase = bHiBase + 16384;
            const uint32_t aHiBase = sb + OFF_AHI;
            const uint32_t aLoBase = sb + OFF_ALO;
#pragma unroll
            for (int ks = 0; ks < 4; ks++) {
                const int k0 = ks * 16;
                uint32_t bhi[4][2], blo[4][2];
#pragma unroll
                for (int p = 0; p < 2; p++) {
                    uint32_t r0, r1, r2, r3;
                    ldsm4(r0, r1, r2, r3, tile_addr(bHiBase, lane, wn + p * 16, k0));
                    bhi[2 * p][0] = r0;     bhi[2 * p][1] = r2;
                    bhi[2 * p + 1][0] = r1; bhi[2 * p + 1][1] = r3;
                    ldsm4(r0, r1, r2, r3, tile_addr(bLoBase, lane, wn + p * 16, k0));
                    blo[2 * p][0] = r0;     blo[2 * p][1] = r2;
                    blo[2 * p + 1][0] = r1; blo[2 * p + 1][1] = r3;
                }
                // double-buffered A fragments: prefetch i+1 before mma of i
                uint32_t ahi[2][4], alo[2][4];
                ldsm4(ahi[0][0], ahi[0][1], ahi[0][2], ahi[0][3],
                      tile_addr(aHiBase, lane, wm, k0));
                ldsm4(alo[0][0], alo[0][1], alo[0][2], alo[0][3],
                      tile_addr(aLoBase, lane, wm, k0));
#pragma unroll
                for (int i = 0; i < 4; i++) {
                    const int cur = i & 1, nxt = cur ^ 1;
                    if (i < 3) {
                        ldsm4(ahi[nxt][0], ahi[nxt][1], ahi[nxt][2], ahi[nxt][3],
                              tile_addr(aHiBase, lane, wm + (i + 1) * 16, k0));
                        ldsm4(alo[nxt][0], alo[nxt][1], alo[nxt][2], alo[nxt][3],
                              tile_addr(aLoBase, lane, wm + (i + 1) * 16, k0));
                    }
#pragma unroll
                    for (int j = 0; j < 4; j++) mma16816(acc[i][j], ahi[cur], bhi[j]);
#pragma unroll
                    for (int j = 0; j < 4; j++) mma16816(acc[i][j], ahi[cur], blo[j]);
#pragma unroll
                    for (int j = 0; j < 4; j++) mma16816(acc[i][j], alo[cur], bhi[j]);
                }
            }
        }

        // ---- epilogue: bias (+ residual), direct register->gmem ----
#pragma unroll
        for (int i = 0; i < 4; i++) {
#pragma unroll
            for (int half = 0; half < 2; half++) {
                int gi = rowBase + wm + i * 16 + tr + half * 8;
                if (gi >= NN) continue;
#pragma unroll
                for (int j = 0; j < 4; j++) {
                    int col = wn + j * 8 + tc;
                    float2 o;
                    o.x = acc[i][j][half * 2]     + bsh[col];
                    o.y = acc[i][j][half * 2 + 1] + bsh[col + 1];
                    if (RES) {
                        float2 rv = __ldg((const float2*)(h + (size_t)gi * DD + col));
                        o.x += rv.x; o.y += rv.y;
                    }
                    *(float2*)(out + (size_t)gi * DD + col) = o;
                }
            }
        }
    }
}

// ---------------- launch ----------------
extern "C" void kernel_launch(void* const* d_in, const int* in_sizes, int n_in,
                              void* d_out, int out_size) {
    const float* x    = (const float*)d_in[0];
    const int*   erow = (const int*)  d_in[1];
    const int*   ecol = (const int*)  d_in[2];
    const float* Wl0 = (const float*)d_in[3];
    const float* Wr0 = (const float*)d_in[4];
    const float* b0  = (const float*)d_in[5];
    const float* Wl1 = (const float*)d_in[6];
    const float* Wr1 = (const float*)d_in[7];
    const float* b1  = (const float*)d_in[8];
    const float* Wl2 = (const float*)d_in[9];
    const float* Wr2 = (const float*)d_in[10];
    const float* b2  = (const float*)d_in[11];
    float* out = (float*)d_out;

    float *p_x1 = nullptr, *p_x2 = nullptr;
    cudaGetSymbolAddress((void**)&p_x1, g_x1);
    cudaGetSymbolAddress((void**)&p_x2, g_x2);

    cudaFuncSetAttribute(k_gemm_mma<false, false>,
                         cudaFuncAttributeMaxDynamicSharedMemorySize, SMEM_GEMM);
    cudaFuncSetAttribute(k_gemm_mma<true, true>,
                         cudaFuncAttributeMaxDynamicSharedMemorySize, SMEM_GEMM);

    const int edge4Blocks  = (NE / 4 + 255) / 256;      // 782
    const int gatherBlocks = (NN * 32 + 255) / 256;     // 6250

    // setup (zero deg + W pre-split, fused) then CSR build
    k_setup<<<NB + 96, 256>>>(Wl0, Wr0, Wl1, Wr1, Wl2, Wr2);
    k_count_deg<<<edge4Blocks, 256>>>(erow);
    k_scanA<<<NB, 256>>>();
    k_scanC<<<NB, 256>>>();
    k_fill<<<edge4Blocks, 256>>>(erow, ecol);

    // ---- layer 0: x1 = sage(x) ----
    k_gather<false><<<gatherBlocks, 256>>>(x);
    k_gemm_mma<false, false><<<GRID_GEMM, 256, SMEM_GEMM>>>(x, 0, b0, p_x1);

    // ---- layer 1: x2 = sage(relu(x1)) + x1 ----
    k_gather<true><<<gatherBlocks, 256>>>(p_x1);
    k_gemm_mma<true, true><<<GRID_GEMM, 256, SMEM_GEMM>>>(p_x1, 1, b1, p_x2);

    // ---- layer 2: out = sage(relu(x2)) + x2 ----
    k_gather<true><<<gatherBlocks, 256>>>(p_x2);
    k_gemm_mma<true, true><<<GRID_GEMM, 256, SMEM_GEMM>>>(p_x2, 2, b2, out);
}